// round 2
// baseline (speedup 1.0000x reference)
#include <cuda_runtime.h>

// FAVOR+ causal linear attention, chunked formulation.
// B=2, L=4096, H=8, D=64, M=128. Chunk C=64, NC=64 chunks per (b,h).
//
// Phase A (kproj):  qp/kp = relu(ratio * X @ P^T)+1e-3 for each 64-token chunk;
//                   also S_c = kp_chunk^T @ V_chunk (MxD) and ksum_c (M).
// Phase B (kscan):  exclusive prefix sum of S_c / ksum_c over chunks, per (b,h).
// Phase C (kout):   A = qp@kp^T (causal mask, inclusive), num = A@V + qp@KVstate,
//                   den = rowsum(A) + qp@ksum_state, out = num/den.

#define BB 2
#define LL 4096
#define HH 8
#define DD 64
#define MM 128
#define CC 64
#define NCH (LL / CC)   // 64
#define BH (BB * HH)    // 16

#define RATIO 0.08838834764831843f   // 1/sqrt(128)
#define STAB  1e-3f

// Scratch (device globals: allocation-free per harness rules)
__device__ float g_qp[(size_t)BH * LL * MM];       // [bh][l][m]  32 MB
__device__ float g_kp[(size_t)BH * LL * MM];       // [bh][l][m]  32 MB
__device__ float g_S [(size_t)BH * NCH * MM * DD]; // [bh][c][m][d] local sums -> exclusive states, 32 MB
__device__ float g_ks[BH * NCH * MM];              // [bh][c][m]

// ---------------------------------------------------------------------------
// Phase A: projection + per-chunk KV sums. grid (NC, BH), 256 threads.
// smem: sPT[64][129] (P transposed, padded), sQ/sK/sV[64][64], sKP[64][128]
// ---------------------------------------------------------------------------
__global__ __launch_bounds__(256) void kproj(const float* __restrict__ q,
                                             const float* __restrict__ k,
                                             const float* __restrict__ v,
                                             const float* __restrict__ P) {
    extern __shared__ float sm[];
    float* sPT = sm;                 // 64*129 = 8256
    float* sQ  = sPT + 64 * 129;     // 4096
    float* sK  = sQ + 4096;          // 4096
    float* sV  = sK + 4096;          // 4096
    float* sKP = sV + 4096;          // 64*128 = 8192

    const int c = blockIdx.x, bh = blockIdx.y;
    const int b = bh / HH, h = bh % HH;
    const int tid = threadIdx.x;
    const int w = tid >> 5, lane = tid & 31;
    const int l0 = c * CC;

    // Load P [M,D] transposed into sPT[d][m] (pad 129 -> conflict-free both ways)
#pragma unroll
    for (int i = 0; i < 8; i++) {
        int idx4 = tid + i * 256;           // 2048 float4s
        int m = idx4 >> 4;
        int d0 = (idx4 & 15) << 2;
        float4 pv = ((const float4*)P)[idx4];
        sPT[(d0 + 0) * 129 + m] = pv.x;
        sPT[(d0 + 1) * 129 + m] = pv.y;
        sPT[(d0 + 2) * 129 + m] = pv.z;
        sPT[(d0 + 3) * 129 + m] = pv.w;
    }
    // Load q/k/v chunk tiles [64 tokens][64]
#pragma unroll
    for (int i = 0; i < 4; i++) {
        int idx4 = tid + i * 256;           // 1024 float4s
        int t = idx4 >> 4;
        int d0 = idx4 & 15;
        size_t g = ((size_t)(b * LL + l0 + t) * HH + h) * (DD / 4) + d0;
        ((float4*)sQ)[t * 16 + d0] = ((const float4*)q)[g];
        ((float4*)sK)[t * 16 + d0] = ((const float4*)k)[g];
        ((float4*)sV)[t * 16 + d0] = ((const float4*)v)[g];
    }
    __syncthreads();

    // Projection: warp w handles tokens t = w*8..w*8+7; lane covers m = lane+32k.
    for (int which = 0; which < 2; which++) {
        const float* sS = which ? sK : sQ;
        float acc[8][4];
#pragma unroll
        for (int i = 0; i < 8; i++) { acc[i][0]=0; acc[i][1]=0; acc[i][2]=0; acc[i][3]=0; }
#pragma unroll 4
        for (int d = 0; d < 64; d++) {
            float p0 = sPT[d * 129 + lane];
            float p1 = sPT[d * 129 + lane + 32];
            float p2 = sPT[d * 129 + lane + 64];
            float p3 = sPT[d * 129 + lane + 96];
#pragma unroll
            for (int i = 0; i < 8; i++) {
                float qv = sS[(w * 8 + i) * 64 + d];   // broadcast
                acc[i][0] += qv * p0; acc[i][1] += qv * p1;
                acc[i][2] += qv * p2; acc[i][3] += qv * p3;
            }
        }
        float* gdst = which ? g_kp : g_qp;
        size_t base = ((size_t)bh * LL + l0) * MM;
#pragma unroll
        for (int i = 0; i < 8; i++) {
            int t = w * 8 + i;
#pragma unroll
            for (int kk = 0; kk < 4; kk++) {
                float val = fmaxf(acc[i][kk] * RATIO, 0.f) + STAB;
                int m = lane + kk * 32;
                gdst[base + (size_t)t * MM + m] = val;
                if (which) sKP[t * MM + m] = val;
            }
        }
    }
    __syncthreads();

    // S_c[m][d] = sum_t kp[t][m]*v[t][d]. Warp w -> m = w*16+i, lane -> d, d+32.
    float accS[16][2];
#pragma unroll
    for (int i = 0; i < 16; i++) { accS[i][0] = 0; accS[i][1] = 0; }
#pragma unroll 4
    for (int t = 0; t < 64; t++) {
        float v0 = sV[t * 64 + lane];
        float v1 = sV[t * 64 + lane + 32];
#pragma unroll
        for (int i = 0; i < 16; i++) {
            float kv = sKP[t * MM + w * 16 + i];       // broadcast
            accS[i][0] += kv * v0; accS[i][1] += kv * v1;
        }
    }
    size_t sbase = ((size_t)bh * NCH + c) * (MM * DD);
#pragma unroll
    for (int i = 0; i < 16; i++) {
        int m = w * 16 + i;
        g_S[sbase + m * 64 + lane]      = accS[i][0];
        g_S[sbase + m * 64 + lane + 32] = accS[i][1];
    }
    if (tid < MM) {
        float s = 0;
#pragma unroll 8
        for (int t = 0; t < 64; t++) s += sKP[t * MM + tid];
        g_ks[(bh * NCH + c) * MM + tid] = s;
    }
}

// ---------------------------------------------------------------------------
// Phase B: exclusive prefix scan over chunks. grid = BH*8, 256 threads.
// ---------------------------------------------------------------------------
__global__ void kscan() {
    const int bh = blockIdx.x >> 3;
    const int part = blockIdx.x & 7;
    const int tid = threadIdx.x;
    const int e0 = part * 1024 + tid;   // covers 1024 of the 8192 (m,d) elements
    float carry[4] = {0, 0, 0, 0};
    for (int c = 0; c < NCH; c++) {
        size_t base = ((size_t)bh * NCH + c) * (MM * DD);
        float tmp[4];
#pragma unroll
        for (int kk = 0; kk < 4; kk++) tmp[kk] = g_S[base + e0 + kk * 256];
#pragma unroll
        for (int kk = 0; kk < 4; kk++) {
            g_S[base + e0 + kk * 256] = carry[kk];
            carry[kk] += tmp[kk];
        }
    }
    if (part == 0 && tid < MM) {
        float cr = 0;
        for (int c = 0; c < NCH; c++) {
            int idx = (bh * NCH + c) * MM + tid;
            float t = g_ks[idx]; g_ks[idx] = cr; cr += t;
        }
    }
}

// ---------------------------------------------------------------------------
// Phase C: per-chunk output. grid (NC, BH), 256 threads.
// smem: sQPT/sKPT[128][65] (transposed qp/kp), sV[64][64], sKV[128][64],
//       sA[64][65], sKS[128], sDen[64]
// ---------------------------------------------------------------------------
__global__ __launch_bounds__(256) void kout(const float* __restrict__ v,
                                            float* __restrict__ out) {
    extern __shared__ float sm[];
    float* sQPT = sm;                   // 128*65 = 8320
    float* sKPT = sQPT + 128 * 65;      // 8320
    float* sV   = sKPT + 128 * 65;      // 4096
    float* sKV  = sV + 4096;            // 8192
    float* sA   = sKV + 8192;           // 64*65 = 4160
    float* sKS  = sA + 64 * 65;         // 128
    float* sDen = sKS + 128;            // 64

    const int c = blockIdx.x, bh = blockIdx.y;
    const int b = bh / HH, h = bh % HH;
    const int tid = threadIdx.x, w = tid >> 5, lane = tid & 31;
    const int l0 = c * CC;

    // qp/kp chunk -> transposed smem (pad 65)
    size_t qb = ((size_t)bh * LL + l0) * MM;
#pragma unroll
    for (int i = 0; i < 8; i++) {
        int idx4 = tid + i * 256;          // 2048 float4s; 32 per token row
        int t = idx4 >> 5;
        int m0 = (idx4 & 31) << 2;
        float4 a = ((const float4*)(g_qp + qb))[idx4];
        sQPT[(m0 + 0) * 65 + t] = a.x; sQPT[(m0 + 1) * 65 + t] = a.y;
        sQPT[(m0 + 2) * 65 + t] = a.z; sQPT[(m0 + 3) * 65 + t] = a.w;
        float4 bb = ((const float4*)(g_kp + qb))[idx4];
        sKPT[(m0 + 0) * 65 + t] = bb.x; sKPT[(m0 + 1) * 65 + t] = bb.y;
        sKPT[(m0 + 2) * 65 + t] = bb.z; sKPT[(m0 + 3) * 65 + t] = bb.w;
    }
    // V chunk
#pragma unroll
    for (int i = 0; i < 4; i++) {
        int idx4 = tid + i * 256;
        int t = idx4 >> 4; int d0 = idx4 & 15;
        size_t g = ((size_t)(b * LL + l0 + t) * HH + h) * (DD / 4) + d0;
        ((float4*)sV)[t * 16 + d0] = ((const float4*)v)[g];
    }
    // KV state (exclusive prefix)
    size_t sbase = ((size_t)bh * NCH + c) * (MM * DD);
#pragma unroll
    for (int i = 0; i < 8; i++) {
        int idx4 = tid + i * 256;
        ((float4*)sKV)[idx4] = ((const float4*)(g_S + sbase))[idx4];
    }
    if (tid < MM) sKS[tid] = g_ks[(bh * NCH + c) * MM + tid];
    __syncthreads();

    // A[t][s] = sum_m qp[t][m]*kp[s][m], causal mask (s <= t)
    float accA[8][2];
#pragma unroll
    for (int i = 0; i < 8; i++) { accA[i][0] = 0; accA[i][1] = 0; }
#pragma unroll 4
    for (int m = 0; m < 128; m++) {
        float k0 = sKPT[m * 65 + lane];
        float k1 = sKPT[m * 65 + lane + 32];
#pragma unroll
        for (int i = 0; i < 8; i++) {
            float qv = sQPT[m * 65 + (w * 8 + i)];     // broadcast
            accA[i][0] += qv * k0; accA[i][1] += qv * k1;
        }
    }
#pragma unroll
    for (int i = 0; i < 8; i++) {
        int t = w * 8 + i;
        sA[t * 65 + lane]      = (lane      <= t) ? accA[i][0] : 0.f;
        sA[t * 65 + lane + 32] = (lane + 32 <= t) ? accA[i][1] : 0.f;
    }
    __syncthreads();

    // num = qp @ KVstate + A @ V
    float accN[8][2];
#pragma unroll
    for (int i = 0; i < 8; i++) { accN[i][0] = 0; accN[i][1] = 0; }
#pragma unroll 4
    for (int m = 0; m < 128; m++) {
        float kv0 = sKV[m * 64 + lane];
        float kv1 = sKV[m * 64 + lane + 32];
#pragma unroll
        for (int i = 0; i < 8; i++) {
            float qv = sQPT[m * 65 + (w * 8 + i)];
            accN[i][0] += qv * kv0; accN[i][1] += qv * kv1;
        }
    }
    const int smax = w * 8 + 8;   // s > max t in this warp contributes 0
    for (int s = 0; s < smax; s++) {
        float v0 = sV[s * 64 + lane];
        float v1 = sV[s * 64 + lane + 32];
#pragma unroll
        for (int i = 0; i < 8; i++) {
            float a = sA[(w * 8 + i) * 65 + s];        // broadcast (0 if s>t)
            accN[i][0] += a * v0; accN[i][1] += a * v1;
        }
    }

    // den[t] = qp[t]·ksum_state + rowsum(A[t][:])
    if (tid < 64) {
        int t = tid;
        float dacc = 0;
#pragma unroll 8
        for (int m = 0; m < 128; m++) dacc += sQPT[m * 65 + t] * sKS[m];
        for (int s = 0; s <= t; s++) dacc += sA[t * 65 + s];
        sDen[t] = dacc;
    }
    __syncthreads();

#pragma unroll
    for (int i = 0; i < 8; i++) {
        int t = w * 8 + i;
        float inv = 1.0f / sDen[t];
        size_t g = ((size_t)(b * LL + l0 + t) * HH + h) * DD;
        out[g + lane]      = accN[i][0] * inv;
        out[g + lane + 32] = accN[i][1] * inv;
    }
}

// ---------------------------------------------------------------------------
extern "C" void kernel_launch(void* const* d_in, const int* in_sizes, int n_in,
                              void* d_out, int out_size) {
    const float* q = (const float*)d_in[0];
    const float* k = (const float*)d_in[1];
    const float* v = (const float*)d_in[2];
    const float* P = (const float*)d_in[3];
    float* out = (float*)d_out;

    const int smA = (64 * 129 + 3 * 4096 + 64 * 128) * (int)sizeof(float);          // 114944 B
    const int smC = (2 * 128 * 65 + 4096 + 8192 + 64 * 65 + 128 + 64) * (int)sizeof(float); // 133120 B

    static bool attrs_set = false;   // host-side only; kernel work is identical every call
    if (!attrs_set) {
        cudaFuncSetAttribute(kproj, cudaFuncAttributeMaxDynamicSharedMemorySize, smA);
        cudaFuncSetAttribute(kout,  cudaFuncAttributeMaxDynamicSharedMemorySize, smC);
        attrs_set = true;
    }

    dim3 grid(NCH, BH);
    kproj<<<grid, 256, smA>>>(q, k, v, P);
    kscan<<<BH * 8, 256>>>();
    kout<<<grid, 256, smC>>>(v, out);
}

// round 3
// speedup vs baseline: 1.2137x; 1.2137x over previous
#include <cuda_runtime.h>

// FAVOR+ causal linear attention, chunked formulation.
// B=2, L=4096, H=8, D=64, M=128. Chunk C=64, NC=64 chunks per (b,h).

#define BB 2
#define LL 4096
#define HH 8
#define DD 64
#define MM 128
#define CC 64
#define NCH (LL / CC)   // 64
#define BH (BB * HH)    // 16

#define RATIO 0.08838834764831843f   // 1/sqrt(128)
#define STAB  1e-3f

__device__ float g_qp[(size_t)BH * LL * MM];       // [bh][l][m]
__device__ float g_kp[(size_t)BH * LL * MM];       // [bh][l][m]
__device__ float g_S [(size_t)BH * NCH * MM * DD]; // [bh][c][m][d]
__device__ float g_ks[BH * NCH * MM];              // [bh][c][m]

// ---------------------------------------------------------------------------
// Phase A: projection + per-chunk KV sums. grid (NC, BH), 256 threads.
// (measured at FFMA floor in R2 — unchanged)
// ---------------------------------------------------------------------------
__global__ __launch_bounds__(256) void kproj(const float* __restrict__ q,
                                             const float* __restrict__ k,
                                             const float* __restrict__ v,
                                             const float* __restrict__ P) {
    extern __shared__ float sm[];
    float* sPT = sm;                 // 64*129
    float* sQ  = sPT + 64 * 129;     // 4096
    float* sK  = sQ + 4096;          // 4096
    float* sV  = sK + 4096;          // 4096
    float* sKP = sV + 4096;          // 64*128

    const int c = blockIdx.x, bh = blockIdx.y;
    const int b = bh / HH, h = bh % HH;
    const int tid = threadIdx.x;
    const int w = tid >> 5, lane = tid & 31;
    const int l0 = c * CC;

#pragma unroll
    for (int i = 0; i < 8; i++) {
        int idx4 = tid + i * 256;
        int m = idx4 >> 4;
        int d0 = (idx4 & 15) << 2;
        float4 pv = ((const float4*)P)[idx4];
        sPT[(d0 + 0) * 129 + m] = pv.x;
        sPT[(d0 + 1) * 129 + m] = pv.y;
        sPT[(d0 + 2) * 129 + m] = pv.z;
        sPT[(d0 + 3) * 129 + m] = pv.w;
    }
#pragma unroll
    for (int i = 0; i < 4; i++) {
        int idx4 = tid + i * 256;
        int t = idx4 >> 4;
        int d0 = idx4 & 15;
        size_t g = ((size_t)(b * LL + l0 + t) * HH + h) * (DD / 4) + d0;
        ((float4*)sQ)[t * 16 + d0] = ((const float4*)q)[g];
        ((float4*)sK)[t * 16 + d0] = ((const float4*)k)[g];
        ((float4*)sV)[t * 16 + d0] = ((const float4*)v)[g];
    }
    __syncthreads();

    for (int which = 0; which < 2; which++) {
        const float* sS = which ? sK : sQ;
        float acc[8][4];
#pragma unroll
        for (int i = 0; i < 8; i++) { acc[i][0]=0; acc[i][1]=0; acc[i][2]=0; acc[i][3]=0; }
#pragma unroll 4
        for (int d = 0; d < 64; d++) {
            float p0 = sPT[d * 129 + lane];
            float p1 = sPT[d * 129 + lane + 32];
            float p2 = sPT[d * 129 + lane + 64];
            float p3 = sPT[d * 129 + lane + 96];
#pragma unroll
            for (int i = 0; i < 8; i++) {
                float qv = sS[(w * 8 + i) * 64 + d];
                acc[i][0] += qv * p0; acc[i][1] += qv * p1;
                acc[i][2] += qv * p2; acc[i][3] += qv * p3;
            }
        }
        float* gdst = which ? g_kp : g_qp;
        size_t base = ((size_t)bh * LL + l0) * MM;
#pragma unroll
        for (int i = 0; i < 8; i++) {
            int t = w * 8 + i;
#pragma unroll
            for (int kk = 0; kk < 4; kk++) {
                float val = fmaxf(acc[i][kk] * RATIO, 0.f) + STAB;
                int m = lane + kk * 32;
                gdst[base + (size_t)t * MM + m] = val;
                if (which) sKP[t * MM + m] = val;
            }
        }
    }
    __syncthreads();

    float accS[16][2];
#pragma unroll
    for (int i = 0; i < 16; i++) { accS[i][0] = 0; accS[i][1] = 0; }
#pragma unroll 4
    for (int t = 0; t < 64; t++) {
        float v0 = sV[t * 64 + lane];
        float v1 = sV[t * 64 + lane + 32];
#pragma unroll
        for (int i = 0; i < 16; i++) {
            float kv = sKP[t * MM + w * 16 + i];
            accS[i][0] += kv * v0; accS[i][1] += kv * v1;
        }
    }
    size_t sbase = ((size_t)bh * NCH + c) * (MM * DD);
#pragma unroll
    for (int i = 0; i < 16; i++) {
        int m = w * 16 + i;
        g_S[sbase + m * 64 + lane]      = accS[i][0];
        g_S[sbase + m * 64 + lane + 32] = accS[i][1];
    }
    if (tid < MM) {
        float s = 0;
#pragma unroll 8
        for (int t = 0; t < 64; t++) s += sKP[t * MM + tid];
        g_ks[(bh * NCH + c) * MM + tid] = s;
    }
}

// ---------------------------------------------------------------------------
// Phase B: exclusive prefix scan over chunks, software-pipelined loads.
// ---------------------------------------------------------------------------
__global__ void kscan() {
    const int bh = blockIdx.x >> 3;
    const int part = blockIdx.x & 7;
    const int tid = threadIdx.x;
    const int e0 = part * 1024 + tid;
    size_t base = (size_t)bh * NCH * (MM * DD);
    float carry[4] = {0, 0, 0, 0};
    float cur[4];
#pragma unroll
    for (int kk = 0; kk < 4; kk++) cur[kk] = g_S[base + e0 + kk * 256];
    for (int c = 0; c < NCH; c++) {
        size_t bc = base + (size_t)c * (MM * DD);
        float nxt[4] = {cur[0], cur[1], cur[2], cur[3]};
        if (c + 1 < NCH) {
#pragma unroll
            for (int kk = 0; kk < 4; kk++) nxt[kk] = g_S[bc + MM * DD + e0 + kk * 256];
        }
#pragma unroll
        for (int kk = 0; kk < 4; kk++) {
            g_S[bc + e0 + kk * 256] = carry[kk];
            carry[kk] += cur[kk];
            cur[kk] = nxt[kk];
        }
    }
    if (part == 0 && tid < MM) {
        float cr = 0;
        float cv = g_ks[bh * NCH * MM + tid];
        for (int c = 0; c < NCH; c++) {
            int idx = (bh * NCH + c) * MM + tid;
            float nv = (c + 1 < NCH) ? g_ks[idx + MM] : 0.f;
            g_ks[idx] = cr; cr += cv; cv = nv;
        }
    }
}

// ---------------------------------------------------------------------------
// Phase C: per-chunk output. grid (NC, BH), 512 threads, 2 CTAs/SM.
// Warp w owns tokens t = 4w..4w+3. A kept in registers (s = 2*lane, 2*lane+1).
// smem 115200 B: sQP[64][128], sKPT (transposed kp, xor-swizzled float2),
// sKV[128][64], sV[64][64], sKS[128].
// ---------------------------------------------------------------------------
__global__ __launch_bounds__(512, 2) void kout(const float* __restrict__ v,
                                               float* __restrict__ out) {
    extern __shared__ float sm[];
    float* sQP  = sm;               // 8192: [t][m] row-major
    float* sKPT = sQP + 8192;       // 8192: (m,s) at m*64 + ((s>>1 ^ (m&31))<<1) + (s&1)
    float* sKV  = sKPT + 8192;      // 8192: [m][d]
    float* sV   = sKV + 8192;       // 4096: [s][d]
    float* sKS  = sV + 4096;        // 128

    const int c = blockIdx.x, bh = blockIdx.y;
    const int b = bh >> 3, h = bh & 7;
    const int tid = threadIdx.x, w = tid >> 5, lane = tid & 31;
    const int l0 = c * CC;

    size_t qb4 = ((size_t)bh * LL + l0) * (MM / 4);
#pragma unroll
    for (int i = 0; i < 4; i++) {
        int idx = tid + i * 512;
        ((float4*)sQP)[idx] = ((const float4*)g_qp)[qb4 + idx];
    }
#pragma unroll
    for (int i = 0; i < 4; i++) {
        int idx = tid + i * 512;
        int t = idx >> 5;                 // 0..63
        int m0 = (idx & 31) << 2;         // 0,4,...,124
        float4 kv4 = ((const float4*)g_kp)[qb4 + idx];
        int hi = (t >> 1), lo = (t & 1);
        sKPT[(m0 + 0) * 64 + (((hi ^ ((m0 + 0) & 31)) << 1) + lo)] = kv4.x;
        sKPT[(m0 + 1) * 64 + (((hi ^ ((m0 + 1) & 31)) << 1) + lo)] = kv4.y;
        sKPT[(m0 + 2) * 64 + (((hi ^ ((m0 + 2) & 31)) << 1) + lo)] = kv4.z;
        sKPT[(m0 + 3) * 64 + (((hi ^ ((m0 + 3) & 31)) << 1) + lo)] = kv4.w;
    }
    size_t sb4 = ((size_t)bh * NCH + c) * (MM * DD / 4);
#pragma unroll
    for (int i = 0; i < 4; i++) {
        int idx = tid + i * 512;
        ((float4*)sKV)[idx] = ((const float4*)g_S)[sb4 + idx];
    }
#pragma unroll
    for (int i = 0; i < 2; i++) {
        int idx = tid + i * 512;
        int t = idx >> 4, d4 = idx & 15;
        ((float4*)sV)[t * 16 + d4] =
            ((const float4*)v)[((size_t)(b * LL + l0 + t) * HH + h) * 16 + d4];
    }
    if (tid < MM) sKS[tid] = g_ks[(bh * NCH + c) * MM + tid];
    __syncthreads();

    const int t0 = w * 4;

    // --- A = qp @ kp^T (this warp's 4 rows; cols s = 2*lane, 2*lane+1) ---
    float2 accA[4] = {{0,0},{0,0},{0,0},{0,0}};
#pragma unroll 8
    for (int m0 = 0; m0 < 128; m0 += 4) {
        float4 qv[4];
#pragma unroll
        for (int i = 0; i < 4; i++) qv[i] = *(const float4*)&sQP[(t0 + i) * 128 + m0];
#pragma unroll
        for (int j = 0; j < 4; j++) {
            int m = m0 + j;
            float2 k01 = *(const float2*)&sKPT[m * 64 + ((lane ^ (m & 31)) << 1)];
#pragma unroll
            for (int i = 0; i < 4; i++) {
                float qj = ((const float*)&qv[i])[j];
                accA[i].x += qj * k01.x;
                accA[i].y += qj * k01.y;
            }
        }
    }
    // causal mask (inclusive s <= t)
#pragma unroll
    for (int i = 0; i < 4; i++) {
        int t = t0 + i;
        if (2 * lane     > t) accA[i].x = 0.f;
        if (2 * lane + 1 > t) accA[i].y = 0.f;
    }

    // --- den[t] = rowsum(A_masked) + qp[t]·ksum_state (butterfly reduce) ---
    float den[4];
#pragma unroll
    for (int i = 0; i < 4; i++) {
        float p = accA[i].x + accA[i].y;
#pragma unroll
        for (int kk = 0; kk < 4; kk++) {
            int m = lane + 32 * kk;
            p += sQP[(t0 + i) * 128 + m] * sKS[m];
        }
#pragma unroll
        for (int off = 16; off > 0; off >>= 1)
            p += __shfl_xor_sync(0xffffffffu, p, off);
        den[i] = p;
    }

    // --- num = qp @ KVstate (d = 2*lane, 2*lane+1) ---
    float2 accN[4] = {{0,0},{0,0},{0,0},{0,0}};
#pragma unroll 8
    for (int m0 = 0; m0 < 128; m0 += 4) {
        float4 qv[4];
#pragma unroll
        for (int i = 0; i < 4; i++) qv[i] = *(const float4*)&sQP[(t0 + i) * 128 + m0];
#pragma unroll
        for (int j = 0; j < 4; j++) {
            int m = m0 + j;
            float2 kv01 = *(const float2*)&sKV[m * 64 + 2 * lane];
#pragma unroll
            for (int i = 0; i < 4; i++) {
                float qj = ((const float*)&qv[i])[j];
                accN[i].x += qj * kv01.x;
                accN[i].y += qj * kv01.y;
            }
        }
    }

    // --- num += A_masked @ V (A broadcast by warp shuffle) ---
    for (int s2 = 0; s2 < 2 * w + 2; s2++) {
        float2 v0 = *(const float2*)&sV[(2 * s2)     * 64 + 2 * lane];
        float2 v1 = *(const float2*)&sV[(2 * s2 + 1) * 64 + 2 * lane];
#pragma unroll
        for (int i = 0; i < 4; i++) {
            float a0 = __shfl_sync(0xffffffffu, accA[i].x, s2);
            float a1 = __shfl_sync(0xffffffffu, accA[i].y, s2);
            accN[i].x += a0 * v0.x; accN[i].y += a0 * v0.y;
            accN[i].x += a1 * v1.x; accN[i].y += a1 * v1.y;
        }
    }

    // --- output ---
#pragma unroll
    for (int i = 0; i < 4; i++) {
        int t = t0 + i;
        float inv = 1.0f / den[i];
        size_t g2 = (((size_t)(b * LL + l0 + t) * HH + h) * DD) / 2 + lane;
        ((float2*)out)[g2] = make_float2(accN[i].x * inv, accN[i].y * inv);
    }
}

// ---------------------------------------------------------------------------
extern "C" void kernel_launch(void* const* d_in, const int* in_sizes, int n_in,
                              void* d_out, int out_size) {
    const float* q = (const float*)d_in[0];
    const float* k = (const float*)d_in[1];
    const float* v = (const float*)d_in[2];
    const float* P = (const float*)d_in[3];
    float* out = (float*)d_out;

    const int smA = (64 * 129 + 3 * 4096 + 64 * 128) * (int)sizeof(float);  // 114944 B
    const int smC = (8192 * 3 + 4096 + 128) * (int)sizeof(float);           // 115200 B

    static bool attrs_set = false;   // host-side only; identical work every call
    if (!attrs_set) {
        cudaFuncSetAttribute(kproj, cudaFuncAttributeMaxDynamicSharedMemorySize, smA);
        cudaFuncSetAttribute(kout,  cudaFuncAttributeMaxDynamicSharedMemorySize, smC);
        attrs_set = true;
    }

    dim3 grid(NCH, BH);
    kproj<<<grid, 256, smA>>>(q, k, v, P);
    kscan<<<BH * 8, 256>>>();
    kout<<<grid, 512, smC>>>(v, out);
}

// round 9
// speedup vs baseline: 1.3506x; 1.1128x over previous
#include <cuda_runtime.h>
#include <cuda_bf16.h>
#include <cstdint>

// FAVOR+ causal linear attention, chunked. B=2,L=4096,H=8,D=64,M=128, C=64.
// R9 (= audited R5 kernel, unchanged through four broker timeouts):
// projection via mma.sync bf16 (split-bf16 x3 = fp32 accuracy).
// tcgen05 unavailable (harness compiles via compute_103 virtual arch).

#define BB 2
#define LL 4096
#define HH 8
#define DD 64
#define MM 128
#define CC 64
#define NCH (LL / CC)   // 64
#define BH (BB * HH)    // 16

#define RATIO 0.08838834764831843f
#define STAB  1e-3f
#define SP 72           // bf16 row stride (conflict-free fragment loads)

__device__ float g_qp[(size_t)BH * LL * MM];
__device__ float g_kp[(size_t)BH * LL * MM];
__device__ float g_S [(size_t)BH * NCH * MM * DD];
__device__ float g_ks[BH * NCH * MM];

// smem byte offsets (kproj): bf16 tiles, stride SP
#define O_QH 0
#define O_QL (O_QH + 64 * SP * 2)    //  9216
#define O_KH (O_QL + 64 * SP * 2)    // 18432
#define O_KL (O_KH + 64 * SP * 2)    // 27648
#define O_PH (O_KL + 64 * SP * 2)    // 36864
#define O_PL (O_PH + 128 * SP * 2)   // 55296
#define SM_A (O_PL + 128 * SP * 2)   // 73728
// aliases after projection: sKP f32 [64][128] at 0 (32768B), sV f32 [64][64] at 32768

__device__ __forceinline__ void split4(float4 f, uint32_t* hi, uint32_t* lo) {
    __nv_bfloat162 h0 = __floats2bfloat162_rn(f.x, f.y);
    __nv_bfloat162 h1 = __floats2bfloat162_rn(f.z, f.w);
    __nv_bfloat162 l0 = __floats2bfloat162_rn(f.x - __bfloat162float(h0.x),
                                              f.y - __bfloat162float(h0.y));
    __nv_bfloat162 l1 = __floats2bfloat162_rn(f.z - __bfloat162float(h1.x),
                                              f.w - __bfloat162float(h1.y));
    hi[0] = *(uint32_t*)&h0; hi[1] = *(uint32_t*)&h1;
    lo[0] = *(uint32_t*)&l0; lo[1] = *(uint32_t*)&l1;
}
__device__ __forceinline__ uint32_t lds1(const char* base, int bf16_idx) {
    return *(const uint32_t*)(base + bf16_idx * 2);
}
__device__ __forceinline__ void mma_bf16(float* d, const uint32_t* a,
                                         uint32_t b0, uint32_t b1) {
    asm volatile("mma.sync.aligned.m16n8k16.row.col.f32.bf16.bf16.f32 "
                 "{%0,%1,%2,%3}, {%4,%5,%6,%7}, {%8,%9}, {%0,%1,%2,%3};"
                 : "+f"(d[0]), "+f"(d[1]), "+f"(d[2]), "+f"(d[3])
                 : "r"(a[0]), "r"(a[1]), "r"(a[2]), "r"(a[3]), "r"(b0), "r"(b1));
}

// ---------------------------------------------------------------------------
// Phase A: mma.sync projection + SIMT S_c. grid (64, 16), 256 threads, 2/SM.
// Warp (wid>>1) -> 16-token slab; (wid&1) -> 64-col half of m.
// ---------------------------------------------------------------------------
__global__ __launch_bounds__(256, 2) void kproj_mma(const float* __restrict__ q,
                                                    const float* __restrict__ k,
                                                    const float* __restrict__ v,
                                                    const float* __restrict__ P) {
    extern __shared__ char smc[];
    float* sKP = (float*)smc;             // alias, used after projection
    float* sV  = (float*)(smc + 32768);   // alias

    const int c = blockIdx.x, bh = blockIdx.y;
    const int b = bh >> 3, h = bh & 7;
    const int tid = threadIdx.x, wid = tid >> 5, lane = tid & 31;
    const int l0 = c * CC;

    // load + split q,k [64 tok][64 d] -> hi/lo bf16 tiles
#pragma unroll
    for (int i = 0; i < 4; i++) {
        int idx4 = tid + i * 256;                 // 1024 float4
        int t = idx4 >> 4, d4 = idx4 & 15;
        size_t gf4 = ((size_t)(b * LL + l0 + t) * HH + h) * 16 + d4;
        uint32_t hi[2], lo[2];
        int o = t * SP + d4 * 4;                  // bf16 index
        split4(((const float4*)q)[gf4], hi, lo);
        *(uint2*)(smc + O_QH + o * 2) = make_uint2(hi[0], hi[1]);
        *(uint2*)(smc + O_QL + o * 2) = make_uint2(lo[0], lo[1]);
        split4(((const float4*)k)[gf4], hi, lo);
        *(uint2*)(smc + O_KH + o * 2) = make_uint2(hi[0], hi[1]);
        *(uint2*)(smc + O_KL + o * 2) = make_uint2(lo[0], lo[1]);
    }
    // load + split P [128 m][64 d]
#pragma unroll
    for (int i = 0; i < 8; i++) {
        int idx4 = tid + i * 256;                 // 2048 float4
        int m = idx4 >> 4, d4 = idx4 & 15;
        uint32_t hi[2], lo[2];
        int o = m * SP + d4 * 4;
        split4(((const float4*)P)[m * 16 + d4], hi, lo);
        *(uint2*)(smc + O_PH + o * 2) = make_uint2(hi[0], hi[1]);
        *(uint2*)(smc + O_PL + o * 2) = make_uint2(lo[0], lo[1]);
    }
    __syncthreads();

    const int t0 = (wid >> 1) * 16;
    const int n0 = (wid & 1) * 64;
    const int r = lane >> 2, cc2 = (lane & 3) * 2;

    float accQ[8][4], accK[8][4];
#pragma unroll
    for (int nt = 0; nt < 8; nt++)
#pragma unroll
        for (int j = 0; j < 4; j++) { accQ[nt][j] = 0.f; accK[nt][j] = 0.f; }

    const char* XQ[3] = {smc + O_QH, smc + O_QH, smc + O_QL};
    const char* XK[3] = {smc + O_KH, smc + O_KH, smc + O_KL};
    const char* PB[3] = {smc + O_PH, smc + O_PL, smc + O_PH};

#pragma unroll
    for (int p = 0; p < 3; p++) {
#pragma unroll
        for (int ks = 0; ks < 4; ks++) {
            const int k0 = ks * 16;
            const int ra = (t0 + r) * SP + k0 + cc2;
            uint32_t aq[4], ak[4];
            aq[0] = lds1(XQ[p], ra);              aq[1] = lds1(XQ[p], ra + 8 * SP);
            aq[2] = lds1(XQ[p], ra + 8);          aq[3] = lds1(XQ[p], ra + 8 * SP + 8);
            ak[0] = lds1(XK[p], ra);              ak[1] = lds1(XK[p], ra + 8 * SP);
            ak[2] = lds1(XK[p], ra + 8);          ak[3] = lds1(XK[p], ra + 8 * SP + 8);
#pragma unroll
            for (int nt = 0; nt < 8; nt++) {
                const int mb = (n0 + nt * 8 + r) * SP + k0 + cc2;
                uint32_t b0 = lds1(PB[p], mb), b1 = lds1(PB[p], mb + 8);
                mma_bf16(accQ[nt], aq, b0, b1);
                mma_bf16(accK[nt], ak, b0, b1);
            }
        }
    }

    // epilogue q (global only — smem tiles may still be read by other warps)
    {
        size_t row0 = ((size_t)bh * LL + l0 + t0 + r) * MM;
#pragma unroll
        for (int nt = 0; nt < 8; nt++) {
            int m = n0 + nt * 8 + cc2;
            float2 o0, o1;
            o0.x = fmaxf(accQ[nt][0] * RATIO, 0.f) + STAB;
            o0.y = fmaxf(accQ[nt][1] * RATIO, 0.f) + STAB;
            o1.x = fmaxf(accQ[nt][2] * RATIO, 0.f) + STAB;
            o1.y = fmaxf(accQ[nt][3] * RATIO, 0.f) + STAB;
            *(float2*)&g_qp[row0 + m] = o0;
            *(float2*)&g_qp[row0 + 8 * MM + m] = o1;
        }
    }
    __syncthreads();   // all smem reads done; safe to overwrite via aliases

    // epilogue k (global + aliased sKP)
    {
        size_t row0 = ((size_t)bh * LL + l0 + t0 + r) * MM;
#pragma unroll
        for (int nt = 0; nt < 8; nt++) {
            int m = n0 + nt * 8 + cc2;
            float2 o0, o1;
            o0.x = fmaxf(accK[nt][0] * RATIO, 0.f) + STAB;
            o0.y = fmaxf(accK[nt][1] * RATIO, 0.f) + STAB;
            o1.x = fmaxf(accK[nt][2] * RATIO, 0.f) + STAB;
            o1.y = fmaxf(accK[nt][3] * RATIO, 0.f) + STAB;
            *(float2*)&g_kp[row0 + m] = o0;
            *(float2*)&g_kp[row0 + 8 * MM + m] = o1;
            *(float2*)&sKP[(t0 + r) * MM + m] = o0;
            *(float2*)&sKP[(t0 + r + 8) * MM + m] = o1;
        }
    }
    // V chunk -> aliased sV
#pragma unroll
    for (int i = 0; i < 4; i++) {
        int idx = tid + i * 256;
        int t = idx >> 4, d4 = idx & 15;
        ((float4*)sV)[t * 16 + d4] =
            ((const float4*)v)[((size_t)(b * LL + l0 + t) * HH + h) * 16 + d4];
    }
    __syncthreads();

    // S_c[m][d] = sum_t kp[t][m]*v[t][d]  (SIMT; warp wid -> 16 m rows)
    float accS[16][2];
#pragma unroll
    for (int i = 0; i < 16; i++) { accS[i][0] = 0; accS[i][1] = 0; }
#pragma unroll 4
    for (int t = 0; t < 64; t++) {
        float v0 = sV[t * 64 + lane];
        float v1 = sV[t * 64 + lane + 32];
#pragma unroll
        for (int i = 0; i < 16; i++) {
            float kv = sKP[t * MM + wid * 16 + i];
            accS[i][0] += kv * v0; accS[i][1] += kv * v1;
        }
    }
    size_t sb = ((size_t)bh * NCH + c) * (MM * DD);
#pragma unroll
    for (int i = 0; i < 16; i++) {
        int m = wid * 16 + i;
        g_S[sb + m * 64 + lane]      = accS[i][0];
        g_S[sb + m * 64 + lane + 32] = accS[i][1];
    }
    if (tid < MM) {
        float s = 0;
#pragma unroll 8
        for (int t = 0; t < 64; t++) s += sKP[t * MM + tid];
        g_ks[(bh * NCH + c) * MM + tid] = s;
    }
}

// ---------------------------------------------------------------------------
// Phase B: exclusive prefix scan over chunks (pipelined). grid BH*8, 256t.
// ---------------------------------------------------------------------------
__global__ void kscan() {
    const int bh = blockIdx.x >> 3;
    const int part = blockIdx.x & 7;
    const int tid = threadIdx.x;
    const int e0 = part * 1024 + tid;
    size_t base = (size_t)bh * NCH * (MM * DD);
    float carry[4] = {0, 0, 0, 0};
    float cur[4];
#pragma unroll
    for (int kk = 0; kk < 4; kk++) cur[kk] = g_S[base + e0 + kk * 256];
    for (int c = 0; c < NCH; c++) {
        size_t bc = base + (size_t)c * (MM * DD);
        float nxt[4] = {cur[0], cur[1], cur[2], cur[3]};
        if (c + 1 < NCH) {
#pragma unroll
            for (int kk = 0; kk < 4; kk++) nxt[kk] = g_S[bc + MM * DD + e0 + kk * 256];
        }
#pragma unroll
        for (int kk = 0; kk < 4; kk++) {
            g_S[bc + e0 + kk * 256] = carry[kk];
            carry[kk] += cur[kk];
            cur[kk] = nxt[kk];
        }
    }
    if (part == 0 && tid < MM) {
        float cr = 0;
        float cv = g_ks[bh * NCH * MM + tid];
        for (int c = 0; c < NCH; c++) {
            int idx = (bh * NCH + c) * MM + tid;
            float nv = (c + 1 < NCH) ? g_ks[idx + MM] : 0.f;
            g_ks[idx] = cr; cr += cv; cv = nv;
        }
    }
}

// ---------------------------------------------------------------------------
// Phase C: per-chunk output. grid (NC, BH), 512 threads, 2 CTAs/SM. (R3)
// ---------------------------------------------------------------------------
__global__ __launch_bounds__(512, 2) void kout(const float* __restrict__ v,
                                               float* __restrict__ out) {
    extern __shared__ float sm[];
    float* sQP  = sm;               // 8192: [t][m]
    float* sKPT = sQP + 8192;       // 8192 swizzled transposed kp
    float* sKV  = sKPT + 8192;      // 8192: [m][d]
    float* sV   = sKV + 8192;       // 4096: [s][d]
    float* sKS  = sV + 4096;        // 128

    const int c = blockIdx.x, bh = blockIdx.y;
    const int b = bh >> 3, h = bh & 7;
    const int tid = threadIdx.x, w = tid >> 5, lane = tid & 31;
    const int l0 = c * CC;

    size_t qb4 = ((size_t)bh * LL + l0) * (MM / 4);
#pragma unroll
    for (int i = 0; i < 4; i++) {
        int idx = tid + i * 512;
        ((float4*)sQP)[idx] = ((const float4*)g_qp)[qb4 + idx];
    }
#pragma unroll
    for (int i = 0; i < 4; i++) {
        int idx = tid + i * 512;
        int t = idx >> 5;
        int m0 = (idx & 31) << 2;
        float4 kv4 = ((const float4*)g_kp)[qb4 + idx];
        int hi = (t >> 1), lo = (t & 1);
        sKPT[(m0 + 0) * 64 + (((hi ^ ((m0 + 0) & 31)) << 1) + lo)] = kv4.x;
        sKPT[(m0 + 1) * 64 + (((hi ^ ((m0 + 1) & 31)) << 1) + lo)] = kv4.y;
        sKPT[(m0 + 2) * 64 + (((hi ^ ((m0 + 2) & 31)) << 1) + lo)] = kv4.z;
        sKPT[(m0 + 3) * 64 + (((hi ^ ((m0 + 3) & 31)) << 1) + lo)] = kv4.w;
    }
    size_t sb4 = ((size_t)bh * NCH + c) * (MM * DD / 4);
#pragma unroll
    for (int i = 0; i < 4; i++) {
        int idx = tid + i * 512;
        ((float4*)sKV)[idx] = ((const float4*)g_S)[sb4 + idx];
    }
#pragma unroll
    for (int i = 0; i < 2; i++) {
        int idx = tid + i * 512;
        int t = idx >> 4, d4 = idx & 15;
        ((float4*)sV)[t * 16 + d4] =
            ((const float4*)v)[((size_t)(b * LL + l0 + t) * HH + h) * 16 + d4];
    }
    if (tid < MM) sKS[tid] = g_ks[(bh * NCH + c) * MM + tid];
    __syncthreads();

    const int t0 = w * 4;
    float2 accA[4] = {{0,0},{0,0},{0,0},{0,0}};
#pragma unroll 8
    for (int m0 = 0; m0 < 128; m0 += 4) {
        float4 qv[4];
#pragma unroll
        for (int i = 0; i < 4; i++) qv[i] = *(const float4*)&sQP[(t0 + i) * 128 + m0];
#pragma unroll
        for (int j = 0; j < 4; j++) {
            int m = m0 + j;
            float2 k01 = *(const float2*)&sKPT[m * 64 + ((lane ^ (m & 31)) << 1)];
#pragma unroll
            for (int i = 0; i < 4; i++) {
                float qj = ((const float*)&qv[i])[j];
                accA[i].x += qj * k01.x;
                accA[i].y += qj * k01.y;
            }
        }
    }
#pragma unroll
    for (int i = 0; i < 4; i++) {
        int t = t0 + i;
        if (2 * lane     > t) accA[i].x = 0.f;
        if (2 * lane + 1 > t) accA[i].y = 0.f;
    }

    float den[4];
#pragma unroll
    for (int i = 0; i < 4; i++) {
        float p = accA[i].x + accA[i].y;
#pragma unroll
        for (int kk = 0; kk < 4; kk++) {
            int m = lane + 32 * kk;
            p += sQP[(t0 + i) * 128 + m] * sKS[m];
        }
#pragma unroll
        for (int off = 16; off > 0; off >>= 1)
            p += __shfl_xor_sync(0xffffffffu, p, off);
        den[i] = p;
    }

    float2 accN[4] = {{0,0},{0,0},{0,0},{0,0}};
#pragma unroll 8
    for (int m0 = 0; m0 < 128; m0 += 4) {
        float4 qv[4];
#pragma unroll
        for (int i = 0; i < 4; i++) qv[i] = *(const float4*)&sQP[(t0 + i) * 128 + m0];
#pragma unroll
        for (int j = 0; j < 4; j++) {
            int m = m0 + j;
            float2 kv01 = *(const float2*)&sKV[m * 64 + 2 * lane];
#pragma unroll
            for (int i = 0; i < 4; i++) {
                float qj = ((const float*)&qv[i])[j];
                accN[i].x += qj * kv01.x;
                accN[i].y += qj * kv01.y;
            }
        }
    }

    for (int s2 = 0; s2 < 2 * w + 2; s2++) {
        float2 v0 = *(const float2*)&sV[(2 * s2)     * 64 + 2 * lane];
        float2 v1 = *(const float2*)&sV[(2 * s2 + 1) * 64 + 2 * lane];
#pragma unroll
        for (int i = 0; i < 4; i++) {
            float a0 = __shfl_sync(0xffffffffu, accA[i].x, s2);
            float a1 = __shfl_sync(0xffffffffu, accA[i].y, s2);
            accN[i].x += a0 * v0.x; accN[i].y += a0 * v0.y;
            accN[i].x += a1 * v1.x; accN[i].y += a1 * v1.y;
        }
    }

#pragma unroll
    for (int i = 0; i < 4; i++) {
        int t = t0 + i;
        float inv = 1.0f / den[i];
        size_t g2 = (((size_t)(b * LL + l0 + t) * HH + h) * DD) / 2 + lane;
        ((float2*)out)[g2] = make_float2(accN[i].x * inv, accN[i].y * inv);
    }
}

// ---------------------------------------------------------------------------
extern "C" void kernel_launch(void* const* d_in, const int* in_sizes, int n_in,
                              void* d_out, int out_size) {
    const float* q = (const float*)d_in[0];
    const float* k = (const float*)d_in[1];
    const float* v = (const float*)d_in[2];
    const float* P = (const float*)d_in[3];
    float* out = (float*)d_out;

    const int smA = SM_A;                                           // 73728 B
    const int smC = (8192 * 3 + 4096 + 128) * (int)sizeof(float);   // 115200 B

    static bool attrs_set = false;
    if (!attrs_set) {
        cudaFuncSetAttribute(kproj_mma, cudaFuncAttributeMaxDynamicSharedMemorySize, smA);
        cudaFuncSetAttribute(kout,      cudaFuncAttributeMaxDynamicSharedMemorySize, smC);
        attrs_set = true;
    }

    kproj_mma<<<dim3(NCH, BH), 256, smA>>>(q, k, v, P);
    kscan<<<BH * 8, 256>>>();
    kout<<<dim3(NCH, BH), 512, smC>>>(v, out);
}